// round 14
// baseline (speedup 1.0000x reference)
#include <cuda_runtime.h>
#include <math.h>
#include <float.h>

// ---------------- problem constants ----------------
#define BS   16
#define TT   50
#define NA   3
#define NC   80
#define HH   76
#define WW   76
#define NCH  255
#define HW   (HH*WW)                              // 5776
#define CELLS_PER_B (NA*HW)                       // 17328
#define TPB  256
#define BLKS_PER_B ((CELLS_PER_B + TPB - 1)/TPB)  // 68
#define NBLK (BS*BLKS_PER_B)                      // 1088
#define FINF FLT_MAX

// ln-domain window: IoU>=0.5 => |ln(ta)-ln(pa)| <= ln2 = 0.6931; use 0.6955 (conservative)
#define LN_WIN 0.6955f
// bucket quantization of ln(area): 64 buckets of width 0.25 over [-8, 8] (monotone, clamped)
#define BBASE  (-8.0f)
#define BINV   (4.0f)

// ---------------- device scratch (static, no allocations) ----------------
__device__ float    g_part[7*NBLK];               // per-block partial sums
__device__ float    g_nobj_part[BS];              // per-image valid-target counts
__device__ unsigned g_count;                      // completion ticket (self-resetting)

// scaled anchors (TOTAL / STRIDE=8)
__constant__ float c_staw[9] = {1.25f, 2.0f, 4.125f, 3.75f, 7.75f, 7.375f, 14.5f, 19.5f, 46.625f};
__constant__ float c_stah[9] = {1.625f, 3.75f, 2.875f, 7.625f, 5.625f, 14.875f, 11.25f, 24.75f, 40.75f};
__constant__ float c_saw[3]  = {1.25f, 2.0f, 4.125f};
__constant__ float c_sah[3]  = {1.625f, 3.75f, 2.875f};
__constant__ float c_lapq[3] = {0.7086512f, 2.0149030f, 2.4731199f};  // ln(saw*sah)

// ---------------- helpers ----------------
__device__ __forceinline__ float softplus(float z) {          // == bce(sigmoid(z), 0)
    return __logf(1.0f + __expf(z));
}
__device__ __forceinline__ float sigm(float z) {
    return __fdividef(1.0f, 1.0f + __expf(-z));
}
__device__ __forceinline__ float safelog(float p) { return p > 0.f ? __logf(p) : -100.0f; }
__device__ __forceinline__ float bce(float p, float t) {
    return -(t * safelog(p) + (1.f - t) * safelog(1.f - p));
}
__device__ __forceinline__ float sl1(float p, float t) {
    float d = fabsf(p - t);
    return d < 1.f ? 0.5f * d * d : d - 0.5f;
}
__device__ __forceinline__ int bucket_of(float la) {
    int k = (int)((la - BBASE) * BINV);
    return min(max(k, 0), 63);
}

// ---------------- the single fused kernel ----------------
__global__ void __launch_bounds__(TPB) yolo_kernel(const float* __restrict__ inp,
                                                   const float* __restrict__ tgt,
                                                   float* __restrict__ out) {
    __shared__ float    s_areaT[TT];        // unsorted areas (rank input)
    __shared__ int      s_rank[TT];         // parallel rank accumulation
    __shared__ float    s_la[64];           // sorted ln(area), FINF-padded
    __shared__ float    s_ar[64];           // sorted areas
    __shared__ float4   s_box[64];          // sorted corners (x1,x2,y1,y2)
    __shared__ float    s_tvals[TT][5];     // tx, ty, tw, th, scale
    __shared__ int      s_tcell[TT];        // owner cell within image or -1
    __shared__ int      s_tcl[TT];          // class index per target
    __shared__ int      s_owner[TPB];       // per-cell owner: 0 or t+1
    __shared__ unsigned s_oc[2];            // 64-bit bucket occupancy
    __shared__ float    s_acc[7];
    __shared__ float    s_nobj;
    __shared__ unsigned s_ticket;
    __shared__ double   s_sum[7];

    int tid = threadIdx.x;
    int b   = blockIdx.x / BLKS_PER_B;
    int c0  = (blockIdx.x % BLKS_PER_B) * TPB;

    // ======== eager loads of the always-needed channels ========
    int local = c0 + tid;
    bool ok = local < CELLS_PER_B;
    int lc = ok ? local : 0;
    int a = lc / HW;
    int r = lc - a * HW;
    int j = r / WW;
    int i = r - j * WW;
    const float* base = inp + (size_t)(b * NCH + a * 85) * HW + r;
    float wv = ok ? base[2*HW] : 0.f;
    float hv = ok ? base[3*HW] : 0.f;
    float zc = ok ? base[4*HW] : 0.f;

    // ---- phase 0: clear shared ----
    s_owner[tid] = 0;
    if (tid < 7)  s_acc[tid] = 0.f;
    if (tid < TT) s_rank[tid] = 0;
    if (tid >= TT && tid < 64) s_la[tid] = FINF;
    if (tid < 2)  s_oc[tid] = 0u;

    // ---- phase 1: per-target prep (threads 0..49) ----
    float area = FINF, larea = FINF, x1 = 0.f, x2 = 0.f, y1 = 0.f, y2 = 0.f;
    int valid = 0, cell = -1;
    if (tid < TT) {
        const float* p = tgt + (size_t)(b * TT + tid) * 5;
        float t0 = p[0], t1 = p[1], t2 = p[2], t3 = p[3], t4 = p[4];
        valid = ((t0 + t1 + t2 + t3 + t4) != 0.f) ? 1 : 0;
        float gx = t1 * (float)WW, gy = t2 * (float)HH;
        float gw = t3 * (float)WW, gh = t4 * (float)HH;
        int gi = (int)gx, gj = (int)gy;

        // anchor match vs 9 total scaled anchors; first-max argmax
        float ga = gw * gh;
        float best = -1e30f; int bestn = 0;
#pragma unroll
        for (int n = 0; n < 9; n++) {
            float inter = fminf(gw, c_staw[n]) * fminf(gh, c_stah[n]);
            float v = inter / (ga + c_staw[n] * c_stah[n] - inter + 1e-16f);
            if (v > best) { best = v; bestn = n; }
        }
        int wr = (valid && bestn < 3) ? bestn : -1;

        x1 = gx - gw * 0.5f; x2 = gx + gw * 0.5f;
        y1 = gy - gh * 0.5f; y2 = gy + gh * 0.5f;
        float ca = (x2 - x1) * (y2 - y1);             // exact reference arithmetic
        area  = valid ? ca : FINF;
        larea = valid ? __logf(ca) : FINF;
        s_areaT[tid] = area;
        s_tcl[tid]   = (int)t0;

        if (wr >= 0) {
            s_tvals[tid][0] = gx - (float)gi;
            s_tvals[tid][1] = gy - (float)gj;
            s_tvals[tid][2] = __logf(gw / c_saw[wr] + 1e-16f);   // ~1e-7 rel err << 1e-3 tol
            s_tvals[tid][3] = __logf(gh / c_sah[wr] + 1e-16f);
            s_tvals[tid][4] = 2.0f - t3 * t4;
            cell = wr * HW + gj * WW + gi;
        }
        s_tcell[tid] = cell;
    }
    int nobj_img = __syncthreads_count(tid < TT && valid);   // also syncs phase 0/1
    if ((blockIdx.x % BLKS_PER_B) == 0 && tid == 0) g_nobj_part[b] = (float)nobj_img;

    // ---- phase 2a: parallel rank-sort (250 threads) + bucket marks + owner scatter ----
    if (tid < TT * 5) {
        int t = tid % TT;
        int c = tid / TT;              // 0..4
        float at = s_areaT[t];
        int cnt = 0;
#pragma unroll
        for (int q = 0; q < 10; q++) {
            int jj = c * 10 + q;
            float aj = s_areaT[jj];
            cnt += (aj < at) || (aj == at && jj < t);   // stable rank
        }
        if (cnt) atomicAdd(&s_rank[t], cnt);
    }
    if (tid < TT && valid)
        atomicOr(&s_oc[bucket_of(larea) >> 5], 1u << (bucket_of(larea) & 31));
    if (cell >= c0 && cell < c0 + TPB)                // last-writer-wins
        atomicMax(&s_owner[cell - c0], tid + 1);
    __syncthreads();

    // ---- phase 2b: scatter into sorted arrays ----
    if (tid < TT) {
        int rank = s_rank[tid];
        s_la[rank]  = larea;
        s_ar[rank]  = area;
        s_box[rank] = make_float4(x1, x2, y1, y2);
    }
    __syncthreads();

    // registers for the double gate
    unsigned occ0 = s_oc[0], occ1 = s_oc[1];
    float lmin = s_la[0];
    float lmax = (nobj_img > 0) ? s_la[nobj_img - 1] : -FINF;

    // ---- phase 3: per-cell loss ----
    float v0 = 0.f, v1 = 0.f, v2 = 0.f, v3 = 0.f, v4 = 0.f, v5 = 0.f, v6 = 0.f;
    bool rare = false;

    if (ok) {
        int owner = s_owner[tid];

        if (owner) {
            // ------ rare: this cell owns a target ------
            rare = true;
            int g = owner - 1;
            float sx = sigm(base[0]);
            float sy = sigm(base[HW]);
            float sc = s_tvals[g][4];
            v0 = sc * bce(sx, s_tvals[g][0]);
            v1 = sc * bce(sy, s_tvals[g][1]);
            v2 = sc * sl1(wv, s_tvals[g][2]);
            v3 = sc * sl1(hv, s_tvals[g][3]);
            v4 = softplus(-zc);                           // bce(conf, 1)
            unsigned m0 = 0, m1 = 0, m2 = 0;
            for (int t = 0; t < TT; t++) {
                if (s_tcell[t] == local) {
                    int c = s_tcl[t];
                    if (c < 32)      m0 |= 1u << c;
                    else if (c < 64) m1 |= 1u << (c - 32);
                    else             m2 |= 1u << (c - 64);
                }
            }
            float s = 0.f;
            for (int c = 0; c < NC; c++) {
                float z = base[(5 + c) * HW];
                unsigned bit = ((c < 32) ? (m0 >> c)
                              : (c < 64) ? (m1 >> (c - 32))
                                         : (m2 >> (c - 64))) & 1u;
                s += softplus(bit ? -z : z);
            }
            v6 = s;
        } else {
            // ------ common: register-only double gate, then search+scan on the ~3% ------
            float lpa = wv + hv + c_lapq[a];              // ln(pred area)
            bool ign = false;
            // gate 1: global ln-area range (2 compares)
            if (lpa >= lmin - LN_WIN && lpa <= lmax + LN_WIN) {
                // gate 2: 64-bucket occupancy in registers
                int bl = bucket_of(lpa - LN_WIN);
                int bu = bucket_of(lpa + LN_WIN);
                unsigned long long occ = ((unsigned long long)occ1 << 32) | occ0;
                unsigned long long wm = ((bu >= 63) ? ~0ull : ((1ull << (bu + 1)) - 1ull))
                                        & ~((1ull << bl) - 1ull);
                if (occ & wm) {
                    // candidate exists: binary search + IoU scan (exact reference math)
                    float lL = lpa - LN_WIN, lU = lpa + LN_WIN;
                    int lo = 0;
#pragma unroll
                    for (int st = 32; st; st >>= 1)
                        if (s_la[lo + st - 1] < lL) lo += st;
                    if (s_la[lo] <= lU) {
                        float sx = sigm(base[0]);         // lazy loads
                        float sy = sigm(base[HW]);
                        float pw = __expf(wv) * c_saw[a];
                        float ph = __expf(hv) * c_sah[a];
                        float px = sx + (float)i, py = sy + (float)j;
                        float px1 = px - pw * 0.5f, px2 = px + pw * 0.5f;
                        float py1 = py - ph * 0.5f, py2 = py + ph * 0.5f;
                        float pa2 = (px2 - px1) * (py2 - py1);
                        for (int idx = lo; idx < 64; idx++) {
                            if (s_la[idx] > lU) break;
                            float4 tb = s_box[idx];
                            float iw = fmaxf(fminf(px2, tb.y) - fmaxf(px1, tb.x), 0.f);
                            float ih = fmaxf(fminf(py2, tb.w) - fmaxf(py1, tb.z), 0.f);
                            float inter = iw * ih;
                            float iou = __fdividef(inter, s_ar[idx] + pa2 - inter + 1e-16f);
                            if (iou >= 0.5f) { ign = true; break; }
                        }
                    }
                }
            }
            if (!ign) v5 = softplus(zc);                  // bce(conf, 0)
        }
    }

    // ---- phase 4: block reduction ----
    unsigned full = 0xffffffffu;
    unsigned anyrare = __ballot_sync(full, rare);
#pragma unroll
    for (int o = 16; o; o >>= 1) v5 += __shfl_down_sync(full, v5, o);
    if (anyrare) {
#pragma unroll
        for (int o = 16; o; o >>= 1) {
            v0 += __shfl_down_sync(full, v0, o);
            v1 += __shfl_down_sync(full, v1, o);
            v2 += __shfl_down_sync(full, v2, o);
            v3 += __shfl_down_sync(full, v3, o);
            v4 += __shfl_down_sync(full, v4, o);
            v6 += __shfl_down_sync(full, v6, o);
        }
    }
    if ((tid & 31) == 0) {
        atomicAdd(&s_acc[5], v5);
        if (anyrare) {
            atomicAdd(&s_acc[0], v0);
            atomicAdd(&s_acc[1], v1);
            atomicAdd(&s_acc[2], v2);
            atomicAdd(&s_acc[3], v3);
            atomicAdd(&s_acc[4], v4);
            atomicAdd(&s_acc[6], v6);
        }
    }
    __syncthreads();
    if (tid < 7) g_part[tid * NBLK + blockIdx.x] = s_acc[tid];
    __syncthreads();                 // all g_part stores done block-wide

    // ---- phase 5: last block finalizes (tid0-only fence) ----
    if (tid == 0) {
        __threadfence();             // orders this block's g_part stores
        s_ticket = atomicAdd(&g_count, 1u);
    }
    __syncthreads();
    if (s_ticket == NBLK - 1) {
        __threadfence();
        int w = tid >> 5, lane = tid & 31;
        if (w < 7) {
            double s = 0.0;
            for (int k = lane; k < NBLK; k += 32) s += (double)g_part[w * NBLK + k];
#pragma unroll
            for (int o = 16; o; o >>= 1) s += __shfl_down_sync(full, s, o);
            if (lane == 0) s_sum[w] = s;
        } else if (w == 7) {
            float nv = (lane < BS) ? g_nobj_part[lane] : 0.f;
#pragma unroll
            for (int o = 16; o; o >>= 1) nv += __shfl_down_sync(full, nv, o);
            if (lane == 0) s_nobj = nv;
        }
        __syncthreads();
        if (tid == 0) {
            g_count = 0;                                   // reset for next graph replay
            double n = (double)s_nobj;
            double lx = s_sum[0] / n, ly = s_sum[1] / n;
            double lw = s_sum[2] / n, lh = s_sum[3] / n;
            double lconf = s_sum[4] / n + 0.5 * (s_sum[5] / n);
            double lcls  = s_sum[6] / n;
            out[0] = (float)(2.5 * (lx + ly) + 2.5 * (lw + lh) + lconf + lcls);
            out[1] = (float)lx;
            out[2] = (float)ly;
            out[3] = (float)lw;
            out[4] = (float)lh;
            out[5] = (float)lconf;
            out[6] = (float)lcls;
        }
    }
}

// ---------------- launch ----------------
extern "C" void kernel_launch(void* const* d_in, const int* in_sizes, int n_in,
                              void* d_out, int out_size) {
    const float* inp = (const float*)d_in[0];
    const float* tgt = (const float*)d_in[1];
    if (n_in >= 2 && in_sizes[0] == BS * TT * 5) {   // identify tensors by size
        const float* tmp = inp; inp = tgt; tgt = tmp;
    }
    float* out = (float*)d_out;

    yolo_kernel<<<NBLK, TPB>>>(inp, tgt, out);
}

// round 15
// speedup vs baseline: 1.0408x; 1.0408x over previous
#include <cuda_runtime.h>
#include <math.h>
#include <float.h>

// ---------------- problem constants ----------------
#define BS   16
#define TT   50
#define NA   3
#define NC   80
#define HH   76
#define WW   76
#define NCH  255
#define HW   (HH*WW)                              // 5776
#define CELLS_PER_B (NA*HW)                       // 17328
#define TPB  256
#define BLKS_PER_B ((CELLS_PER_B + TPB - 1)/TPB)  // 68
#define NBLK (BS*BLKS_PER_B)                      // 1088
#define FINF FLT_MAX

// ---------------- device scratch (static, no allocations) ----------------
__device__ float    g_part[7*NBLK];               // per-block partial sums
__device__ float    g_nobj_part[BS];              // per-image valid-target counts
__device__ unsigned g_count;                      // completion ticket (self-resetting)

// scaled anchors (TOTAL / STRIDE=8)
__constant__ float c_staw[9] = {1.25f, 2.0f, 4.125f, 3.75f, 7.75f, 7.375f, 14.5f, 19.5f, 46.625f};
__constant__ float c_stah[9] = {1.625f, 3.75f, 2.875f, 7.625f, 5.625f, 14.875f, 11.25f, 24.75f, 40.75f};
__constant__ float c_saw[3]  = {1.25f, 2.0f, 4.125f};
__constant__ float c_sah[3]  = {1.625f, 3.75f, 2.875f};
__constant__ float c_apq[3]  = {2.03125f, 7.5f, 11.859375f};  // saw*sah

// ---------------- helpers ----------------
__device__ __forceinline__ float softplus(float z) {          // == bce(sigmoid(z), 0)
    return __logf(1.0f + __expf(z));
}
__device__ __forceinline__ float sigm(float z) {
    return __fdividef(1.0f, 1.0f + __expf(-z));
}
__device__ __forceinline__ float safelog(float p) { return p > 0.f ? __logf(p) : -100.0f; }
__device__ __forceinline__ float bce(float p, float t) {
    return -(t * safelog(p) + (1.f - t) * safelog(1.f - p));
}
__device__ __forceinline__ float sl1(float p, float t) {
    float d = fabsf(p - t);
    return d < 1.f ? 0.5f * d * d : d - 0.5f;
}

// ---------------- the single fused kernel ----------------
__global__ void __launch_bounds__(TPB) yolo_kernel(const float* __restrict__ inp,
                                                   const float* __restrict__ tgt,
                                                   float* __restrict__ out) {
    __shared__ float    s_areaT[TT];        // unsorted areas (rank-sort input)
    __shared__ float    s_area[64];         // sorted ascending, FINF-padded
    __shared__ float4   s_box[64];          // sorted corners (x1,x2,y1,y2)
    __shared__ float    s_tvals[TT][5];     // tx, ty, tw, th, scale
    __shared__ int      s_owner[TPB];       // per-cell owner: 0 or t+1
    __shared__ unsigned s_clsb[TPB][3];     // per-cell class bitmask
    __shared__ float    s_acc[7];
    __shared__ unsigned s_ticket;
    __shared__ double   s_sum[7];

    int tid = threadIdx.x;
    int b   = blockIdx.x / BLKS_PER_B;
    int c0  = (blockIdx.x % BLKS_PER_B) * TPB;   // first cell (within image) of this block

    // ---- phase 0: clear shared ----
    s_owner[tid] = 0;
    s_clsb[tid][0] = 0; s_clsb[tid][1] = 0; s_clsb[tid][2] = 0;
    if (tid < 7) s_acc[tid] = 0.f;
    if (tid >= TT && tid < 64) s_area[tid] = FINF;

    // ---- phase 1: per-target prep (threads 0..49) ----
    float area = FINF, x1 = 0.f, x2 = 0.f, y1 = 0.f, y2 = 0.f;
    int valid = 0, cell = -1, clsi = 0;
    if (tid < TT) {
        const float* p = tgt + (size_t)(b * TT + tid) * 5;
        float t0 = p[0], t1 = p[1], t2 = p[2], t3 = p[3], t4 = p[4];
        valid = ((t0 + t1 + t2 + t3 + t4) != 0.f) ? 1 : 0;
        clsi  = (int)t0;
        float gx = t1 * (float)WW, gy = t2 * (float)HH;
        float gw = t3 * (float)WW, gh = t4 * (float)HH;
        int gi = (int)gx, gj = (int)gy;

        // anchor match vs 9 total scaled anchors; first-max argmax
        float ga = gw * gh;
        float best = -1e30f; int bestn = 0;
#pragma unroll
        for (int n = 0; n < 9; n++) {
            float inter = fminf(gw, c_staw[n]) * fminf(gh, c_stah[n]);
            float v = inter / (ga + c_staw[n] * c_stah[n] - inter + 1e-16f);
            if (v > best) { best = v; bestn = n; }
        }
        int wr = (valid && bestn < 3) ? bestn : -1;

        x1 = gx - gw * 0.5f; x2 = gx + gw * 0.5f;
        y1 = gy - gh * 0.5f; y2 = gy + gh * 0.5f;
        area = valid ? (x2 - x1) * (y2 - y1) : FINF;
        s_areaT[tid] = area;

        if (wr >= 0) {
            s_tvals[tid][0] = gx - (float)gi;
            s_tvals[tid][1] = gy - (float)gj;
            s_tvals[tid][2] = logf(gw / c_saw[wr] + 1e-16f);
            s_tvals[tid][3] = logf(gh / c_sah[wr] + 1e-16f);
            s_tvals[tid][4] = 2.0f - t3 * t4;
            cell = wr * HW + gj * WW + gi;
        }
    }
    // per-image valid count (identical across this image's blocks)
    int nobj_img = __syncthreads_count(tid < TT && valid);  // also syncs phase 0/1
    // first block of each image publishes its image's count
    if ((blockIdx.x % BLKS_PER_B) == 0 && tid == 0) g_nobj_part[b] = (float)nobj_img;

    // ---- phase 2: rank-sort + owner scatter into shared ----
    if (tid < TT) {
        int rank = 0;
        for (int j = 0; j < TT; j++) {
            float aj = s_areaT[j];
            rank += (aj < area) || (aj == area && j < tid);
        }
        s_area[rank] = area;
        s_box[rank]  = make_float4(x1, x2, y1, y2);
        if (cell >= c0 && cell < c0 + TPB) {             // last-writer-wins + class bit OR
            atomicMax(&s_owner[cell - c0], tid + 1);
            atomicOr(&s_clsb[cell - c0][clsi >> 5], 1u << (clsi & 31));
        }
    }
    __syncthreads();

    // ---- phase 3: per-cell loss ----
    float v0 = 0.f, v1 = 0.f, v2 = 0.f, v3 = 0.f, v4 = 0.f, v5 = 0.f, v6 = 0.f;
    bool rare = false;
    int local = c0 + tid;

    if (local < CELLS_PER_B) {
        int a = local / HW;
        int r = local - a * HW;
        int j = r / WW;
        int i = r - j * WW;

        const float* base = inp + (size_t)(b * NCH + a * 85) * HW + r;
        float wv = base[2*HW];
        float hv = base[3*HW];
        float zc = base[4*HW];
        int owner = s_owner[tid];

        if (owner) {
            // ------ rare: this cell owns a target ------
            rare = true;
            int g = owner - 1;
            float sx = sigm(base[0]);
            float sy = sigm(base[HW]);
            float sc = s_tvals[g][4];
            v0 = sc * bce(sx, s_tvals[g][0]);
            v1 = sc * bce(sy, s_tvals[g][1]);
            v2 = sc * sl1(wv, s_tvals[g][2]);
            v3 = sc * sl1(hv, s_tvals[g][3]);
            v4 = softplus(-zc);                           // bce(conf, 1)
            unsigned m0 = s_clsb[tid][0], m1 = s_clsb[tid][1], m2 = s_clsb[tid][2];
            float s = 0.f;
            for (int c = 0; c < NC; c++) {
                float z = base[(5 + c) * HW];
                unsigned bit = ((c < 32) ? (m0 >> c)
                              : (c < 64) ? (m1 >> (c - 32))
                                         : (m2 >> (c - 64))) & 1u;
                s += softplus(bit ? -z : z);
            }
            v6 = s;
        } else {
            // ------ common: ignore test via sorted-area prefilter ------
            float pa  = __expf(wv + hv) * c_apq[a];
            float paL = pa * 0.499f;            // IoU>=0.5 requires target area in [pa/2, 2pa]
            float paU = pa * 2.004f;            // margin >> fp rounding: never wrongly excludes
            int lo = 0;
#pragma unroll
            for (int st = 32; st; st >>= 1)
                if (s_area[lo + st - 1] < paL) lo += st;
            bool ign = false;
            if (s_area[lo] >= paL && s_area[lo] <= paU) {
                float sx = sigm(base[0]);
                float sy = sigm(base[HW]);
                float pw = __expf(wv) * c_saw[a];
                float ph = __expf(hv) * c_sah[a];
                float px = sx + (float)i, py = sy + (float)j;
                float px1 = px - pw * 0.5f, px2 = px + pw * 0.5f;
                float py1 = py - ph * 0.5f, py2 = py + ph * 0.5f;
                float pa2 = (px2 - px1) * (py2 - py1);
                for (int idx = lo; idx < 64; idx++) {
                    float ta = s_area[idx];
                    if (ta > paU) break;
                    float4 tb = s_box[idx];
                    float iw = fmaxf(fminf(px2, tb.y) - fmaxf(px1, tb.x), 0.f);
                    float ih = fmaxf(fminf(py2, tb.w) - fmaxf(py1, tb.z), 0.f);
                    float inter = iw * ih;
                    float iou = __fdividef(inter, ta + pa2 - inter + 1e-16f);
                    if (iou >= 0.5f) { ign = true; break; }
                }
            }
            if (!ign) v5 = softplus(zc);        // bce(conf, 0)
        }
    }

    // ---- phase 4: block reduction ----
    unsigned full = 0xffffffffu;
    unsigned anyrare = __ballot_sync(full, rare);
#pragma unroll
    for (int o = 16; o; o >>= 1) v5 += __shfl_down_sync(full, v5, o);
    if (anyrare) {
#pragma unroll
        for (int o = 16; o; o >>= 1) {
            v0 += __shfl_down_sync(full, v0, o);
            v1 += __shfl_down_sync(full, v1, o);
            v2 += __shfl_down_sync(full, v2, o);
            v3 += __shfl_down_sync(full, v3, o);
            v4 += __shfl_down_sync(full, v4, o);
            v6 += __shfl_down_sync(full, v6, o);
        }
    }
    if ((tid & 31) == 0) {
        atomicAdd(&s_acc[5], v5);
        if (anyrare) {
            atomicAdd(&s_acc[0], v0);
            atomicAdd(&s_acc[1], v1);
            atomicAdd(&s_acc[2], v2);
            atomicAdd(&s_acc[3], v3);
            atomicAdd(&s_acc[4], v4);
            atomicAdd(&s_acc[6], v6);
        }
    }
    __syncthreads();
    if (tid < 7) g_part[tid * NBLK + blockIdx.x] = s_acc[tid];

    // ---- phase 5: last block finalizes ----
    __threadfence();
    if (tid == 0) s_ticket = atomicAdd(&g_count, 1u);
    __syncthreads();
    if (s_ticket == NBLK - 1) {
        __threadfence();
        int w = tid >> 5, lane = tid & 31;
        if (w < 7) {
            double s = 0.0;
            for (int k = lane; k < NBLK; k += 32) s += (double)g_part[w * NBLK + k];
#pragma unroll
            for (int o = 16; o; o >>= 1) s += __shfl_down_sync(full, s, o);
            if (lane == 0) s_sum[w] = s;
        } else if (w == 7) {
            // total valid targets across all images
            float nv = (lane < BS) ? g_nobj_part[lane] : 0.f;
#pragma unroll
            for (int o = 16; o; o >>= 1) nv += __shfl_down_sync(full, nv, o);
            if (lane == 0) s_ticket = __float_as_uint(nv);   // stash total in shared
        }
        __syncthreads();
        if (tid == 0) {
            g_count = 0;                                   // reset for next graph replay
            double n = (double)__uint_as_float(s_ticket);
            double lx = s_sum[0] / n, ly = s_sum[1] / n;
            double lw = s_sum[2] / n, lh = s_sum[3] / n;
            double lconf = s_sum[4] / n + 0.5 * (s_sum[5] / n);
            double lcls  = s_sum[6] / n;
            out[0] = (float)(2.5 * (lx + ly) + 2.5 * (lw + lh) + lconf + lcls);
            out[1] = (float)lx;
            out[2] = (float)ly;
            out[3] = (float)lw;
            out[4] = (float)lh;
            out[5] = (float)lconf;
            out[6] = (float)lcls;
        }
    }
}

// ---------------- launch ----------------
extern "C" void kernel_launch(void* const* d_in, const int* in_sizes, int n_in,
                              void* d_out, int out_size) {
    const float* inp = (const float*)d_in[0];
    const float* tgt = (const float*)d_in[1];
    if (n_in >= 2 && in_sizes[0] == BS * TT * 5) {   // identify tensors by size
        const float* tmp = inp; inp = tgt; tgt = tmp;
    }
    float* out = (float*)d_out;

    yolo_kernel<<<NBLK, TPB>>>(inp, tgt, out);
}

// round 16
// speedup vs baseline: 1.0993x; 1.0562x over previous
#include <cuda_runtime.h>
#include <math.h>
#include <float.h>

// ---------------- problem constants ----------------
#define BS   16
#define TT   50
#define NA   3
#define NC   80
#define HH   76
#define WW   76
#define NCH  255
#define HW   (HH*WW)                              // 5776
#define CELLS_PER_B (NA*HW)                       // 17328
#define TPB  256
#define BLKS_PER_B ((CELLS_PER_B + TPB - 1)/TPB)  // 68
#define NBLK (BS*BLKS_PER_B)                      // 1088
#define FINF FLT_MAX

// ---------------- device scratch (static, no allocations) ----------------
__device__ float    g_part[7*NBLK];               // per-block partial sums
__device__ float    g_nobj_part[BS];              // per-image valid-target counts
__device__ unsigned g_count;                      // completion ticket (self-resetting)

// scaled anchors (TOTAL / STRIDE=8)
__constant__ float c_staw[9] = {1.25f, 2.0f, 4.125f, 3.75f, 7.75f, 7.375f, 14.5f, 19.5f, 46.625f};
__constant__ float c_stah[9] = {1.625f, 3.75f, 2.875f, 7.625f, 5.625f, 14.875f, 11.25f, 24.75f, 40.75f};
__constant__ float c_saw[3]  = {1.25f, 2.0f, 4.125f};
__constant__ float c_sah[3]  = {1.625f, 3.75f, 2.875f};
__constant__ float c_apq[3]  = {2.03125f, 7.5f, 11.859375f};  // saw*sah

// ---------------- helpers ----------------
__device__ __forceinline__ float softplus(float z) {          // == bce(sigmoid(z), 0)
    return __logf(1.0f + __expf(z));
}
__device__ __forceinline__ float sigm(float z) {
    return __fdividef(1.0f, 1.0f + __expf(-z));
}
__device__ __forceinline__ float safelog(float p) { return p > 0.f ? __logf(p) : -100.0f; }
__device__ __forceinline__ float bce(float p, float t) {
    return -(t * safelog(p) + (1.f - t) * safelog(1.f - p));
}
__device__ __forceinline__ float sl1(float p, float t) {
    float d = fabsf(p - t);
    return d < 1.f ? 0.5f * d * d : d - 0.5f;
}

// ---------------- the single fused kernel (R4 base, occupancy-forced) ----------------
__global__ void __launch_bounds__(TPB, 8) yolo_kernel(const float* __restrict__ inp,
                                                      const float* __restrict__ tgt,
                                                      float* __restrict__ out) {
    __shared__ float    s_areaT[TT];        // unsorted areas (rank-sort input)
    __shared__ float    s_area[64];         // sorted ascending, FINF-padded
    __shared__ float4   s_box[64];          // sorted corners (x1,x2,y1,y2)
    __shared__ float    s_tvals[TT][5];     // tx, ty, tw, th, scale
    __shared__ int      s_owner[TPB];       // per-cell owner: 0 or t+1
    __shared__ unsigned s_clsb[TPB][3];     // per-cell class bitmask
    __shared__ float    s_acc[7];
    __shared__ unsigned s_ticket;
    __shared__ double   s_sum[7];

    int tid = threadIdx.x;
    int b   = blockIdx.x / BLKS_PER_B;
    int c0  = (blockIdx.x % BLKS_PER_B) * TPB;   // first cell (within image) of this block

    // ---- phase 0: clear shared ----
    s_owner[tid] = 0;
    s_clsb[tid][0] = 0; s_clsb[tid][1] = 0; s_clsb[tid][2] = 0;
    if (tid < 7) s_acc[tid] = 0.f;
    if (tid >= TT && tid < 64) s_area[tid] = FINF;

    // ---- phase 1: per-target prep (threads 0..49) ----
    float area = FINF, x1 = 0.f, x2 = 0.f, y1 = 0.f, y2 = 0.f;
    int valid = 0, cell = -1, clsi = 0;
    if (tid < TT) {
        const float* p = tgt + (size_t)(b * TT + tid) * 5;
        float t0 = p[0], t1 = p[1], t2 = p[2], t3 = p[3], t4 = p[4];
        valid = ((t0 + t1 + t2 + t3 + t4) != 0.f) ? 1 : 0;
        clsi  = (int)t0;
        float gx = t1 * (float)WW, gy = t2 * (float)HH;
        float gw = t3 * (float)WW, gh = t4 * (float)HH;
        int gi = (int)gx, gj = (int)gy;

        // anchor match vs 9 total scaled anchors; first-max argmax
        float ga = gw * gh;
        float best = -1e30f; int bestn = 0;
#pragma unroll
        for (int n = 0; n < 9; n++) {
            float inter = fminf(gw, c_staw[n]) * fminf(gh, c_stah[n]);
            float v = inter / (ga + c_staw[n] * c_stah[n] - inter + 1e-16f);
            if (v > best) { best = v; bestn = n; }
        }
        int wr = (valid && bestn < 3) ? bestn : -1;

        x1 = gx - gw * 0.5f; x2 = gx + gw * 0.5f;
        y1 = gy - gh * 0.5f; y2 = gy + gh * 0.5f;
        area = valid ? (x2 - x1) * (y2 - y1) : FINF;
        s_areaT[tid] = area;

        if (wr >= 0) {
            s_tvals[tid][0] = gx - (float)gi;
            s_tvals[tid][1] = gy - (float)gj;
            s_tvals[tid][2] = logf(gw / c_saw[wr] + 1e-16f);
            s_tvals[tid][3] = logf(gh / c_sah[wr] + 1e-16f);
            s_tvals[tid][4] = 2.0f - t3 * t4;
            cell = wr * HW + gj * WW + gi;
        }
    }
    // per-image valid count (identical across this image's blocks)
    int nobj_img = __syncthreads_count(tid < TT && valid);  // also syncs phase 0/1
    if ((blockIdx.x % BLKS_PER_B) == 0 && tid == 0) g_nobj_part[b] = (float)nobj_img;

    // ---- phase 2: rank-sort + owner scatter into shared ----
    if (tid < TT) {
        int rank = 0;
        for (int j = 0; j < TT; j++) {
            float aj = s_areaT[j];
            rank += (aj < area) || (aj == area && j < tid);
        }
        s_area[rank] = area;
        s_box[rank]  = make_float4(x1, x2, y1, y2);
        if (cell >= c0 && cell < c0 + TPB) {             // last-writer-wins + class bit OR
            atomicMax(&s_owner[cell - c0], tid + 1);
            atomicOr(&s_clsb[cell - c0][clsi >> 5], 1u << (clsi & 31));
        }
    }
    __syncthreads();

    // ---- phase 3: per-cell loss ----
    float v0 = 0.f, v1 = 0.f, v2 = 0.f, v3 = 0.f, v4 = 0.f, v5 = 0.f, v6 = 0.f;
    bool rare = false;
    int local = c0 + tid;

    if (local < CELLS_PER_B) {
        int a = local / HW;
        int r = local - a * HW;
        int j = r / WW;
        int i = r - j * WW;

        const float* base = inp + (size_t)(b * NCH + a * 85) * HW + r;
        float wv = base[2*HW];
        float hv = base[3*HW];
        float zc = base[4*HW];
        int owner = s_owner[tid];

        if (owner) {
            // ------ rare: this cell owns a target ------
            rare = true;
            int g = owner - 1;
            float sx = sigm(base[0]);
            float sy = sigm(base[HW]);
            float sc = s_tvals[g][4];
            v0 = sc * bce(sx, s_tvals[g][0]);
            v1 = sc * bce(sy, s_tvals[g][1]);
            v2 = sc * sl1(wv, s_tvals[g][2]);
            v3 = sc * sl1(hv, s_tvals[g][3]);
            v4 = softplus(-zc);                           // bce(conf, 1)
            unsigned m0 = s_clsb[tid][0], m1 = s_clsb[tid][1], m2 = s_clsb[tid][2];
            float s = 0.f;
            for (int c = 0; c < NC; c++) {
                float z = base[(5 + c) * HW];
                unsigned bit = ((c < 32) ? (m0 >> c)
                              : (c < 64) ? (m1 >> (c - 32))
                                         : (m2 >> (c - 64))) & 1u;
                s += softplus(bit ? -z : z);
            }
            v6 = s;
        } else {
            // ------ common: ignore test via sorted-area prefilter ------
            float pa  = __expf(wv + hv) * c_apq[a];
            float paL = pa * 0.499f;            // IoU>=0.5 requires target area in [pa/2, 2pa]
            float paU = pa * 2.004f;            // margin >> fp rounding: never wrongly excludes
            int lo = 0;
#pragma unroll
            for (int st = 32; st; st >>= 1)
                if (s_area[lo + st - 1] < paL) lo += st;
            bool ign = false;
            if (s_area[lo] >= paL && s_area[lo] <= paU) {
                float sx = sigm(base[0]);
                float sy = sigm(base[HW]);
                float pw = __expf(wv) * c_saw[a];
                float ph = __expf(hv) * c_sah[a];
                float px = sx + (float)i, py = sy + (float)j;
                float px1 = px - pw * 0.5f, px2 = px + pw * 0.5f;
                float py1 = py - ph * 0.5f, py2 = py + ph * 0.5f;
                float pa2 = (px2 - px1) * (py2 - py1);
                for (int idx = lo; idx < 64; idx++) {
                    float ta = s_area[idx];
                    if (ta > paU) break;
                    float4 tb = s_box[idx];
                    float iw = fmaxf(fminf(px2, tb.y) - fmaxf(px1, tb.x), 0.f);
                    float ih = fmaxf(fminf(py2, tb.w) - fmaxf(py1, tb.z), 0.f);
                    float inter = iw * ih;
                    float iou = __fdividef(inter, ta + pa2 - inter + 1e-16f);
                    if (iou >= 0.5f) { ign = true; break; }
                }
            }
            if (!ign) v5 = softplus(zc);        // bce(conf, 0)
        }
    }

    // ---- phase 4: block reduction ----
    unsigned full = 0xffffffffu;
    unsigned anyrare = __ballot_sync(full, rare);
#pragma unroll
    for (int o = 16; o; o >>= 1) v5 += __shfl_down_sync(full, v5, o);
    if (anyrare) {
#pragma unroll
        for (int o = 16; o; o >>= 1) {
            v0 += __shfl_down_sync(full, v0, o);
            v1 += __shfl_down_sync(full, v1, o);
            v2 += __shfl_down_sync(full, v2, o);
            v3 += __shfl_down_sync(full, v3, o);
            v4 += __shfl_down_sync(full, v4, o);
            v6 += __shfl_down_sync(full, v6, o);
        }
    }
    if ((tid & 31) == 0) {
        atomicAdd(&s_acc[5], v5);
        if (anyrare) {
            atomicAdd(&s_acc[0], v0);
            atomicAdd(&s_acc[1], v1);
            atomicAdd(&s_acc[2], v2);
            atomicAdd(&s_acc[3], v3);
            atomicAdd(&s_acc[4], v4);
            atomicAdd(&s_acc[6], v6);
        }
    }
    __syncthreads();
    if (tid < 7) g_part[tid * NBLK + blockIdx.x] = s_acc[tid];

    // ---- phase 5: last block finalizes ----
    __threadfence();
    if (tid == 0) s_ticket = atomicAdd(&g_count, 1u);
    __syncthreads();
    if (s_ticket == NBLK - 1) {
        __threadfence();
        int w = tid >> 5, lane = tid & 31;
        if (w < 7) {
            double s = 0.0;
            for (int k = lane; k < NBLK; k += 32) s += (double)g_part[w * NBLK + k];
#pragma unroll
            for (int o = 16; o; o >>= 1) s += __shfl_down_sync(full, s, o);
            if (lane == 0) s_sum[w] = s;
        } else if (w == 7) {
            // total valid targets across all images
            float nv = (lane < BS) ? g_nobj_part[lane] : 0.f;
#pragma unroll
            for (int o = 16; o; o >>= 1) nv += __shfl_down_sync(full, nv, o);
            if (lane == 0) s_ticket = __float_as_uint(nv);   // stash total in shared
        }
        __syncthreads();
        if (tid == 0) {
            g_count = 0;                                   // reset for next graph replay
            double n = (double)__uint_as_float(s_ticket);
            double lx = s_sum[0] / n, ly = s_sum[1] / n;
            double lw = s_sum[2] / n, lh = s_sum[3] / n;
            double lconf = s_sum[4] / n + 0.5 * (s_sum[5] / n);
            double lcls  = s_sum[6] / n;
            out[0] = (float)(2.5 * (lx + ly) + 2.5 * (lw + lh) + lconf + lcls);
            out[1] = (float)lx;
            out[2] = (float)ly;
            out[3] = (float)lw;
            out[4] = (float)lh;
            out[5] = (float)lconf;
            out[6] = (float)lcls;
        }
    }
}

// ---------------- launch ----------------
extern "C" void kernel_launch(void* const* d_in, const int* in_sizes, int n_in,
                              void* d_out, int out_size) {
    const float* inp = (const float*)d_in[0];
    const float* tgt = (const float*)d_in[1];
    if (n_in >= 2 && in_sizes[0] == BS * TT * 5) {   // identify tensors by size
        const float* tmp = inp; inp = tgt; tgt = tmp;
    }
    float* out = (float*)d_out;

    yolo_kernel<<<NBLK, TPB>>>(inp, tgt, out);
}